// round 1
// baseline (speedup 1.0000x reference)
#include <cuda_runtime.h>
#include <math.h>

#define S_LEN 2048
#define BATCH 64
#define INSZ  512
#define HID   512
#define BH    (BATCH * HID)          // 32768
#define GATES 1024                   // compact z|n gates
#define M_TOT (S_LEN * BATCH)        // 131072

#define GCTA  128                    // persistent CTAs for recurrence
#define JPER  4                      // hidden units per CTA
#define HPAD  516                    // padded h row stride (floats), conflict-free

// 512 MB scratch for x-projection (z|n gates, bias folded in)
__device__ float g_xp[(size_t)M_TOT * GATES];
__device__ unsigned g_count;
__device__ unsigned g_sense;

__global__ void reset_kernel() {
    g_count = 0u;
    g_sense = 0u;
}

// ---------------------------------------------------------------------------
// Phase 1: C[m][n] = sum_k x[m][k] * Wih[HID + n][k] + bias[HID + n]
// Classic 128x128x8 tiled SGEMM, 256 threads, 8x8 per-thread micro-tile.
// ---------------------------------------------------------------------------
__global__ __launch_bounds__(256) void xproj_kernel(
    const float* __restrict__ A,     // x  [M_TOT, INSZ]
    const float* __restrict__ Wih,   // [3H, INSZ]
    const float* __restrict__ bias)  // [3H]
{
    __shared__ float As[8][128];
    __shared__ float Bs[8][128];

    const int bx  = blockIdx.x;      // n tile (8)
    const int by  = blockIdx.y;      // m tile (1024)
    const int tid = threadIdx.x;

    const int lrow = tid >> 1;           // 0..127
    const int lcol = (tid & 1) * 4;      // 0 or 4

    const float* Aptr = A   + (size_t)(by * 128 + lrow) * INSZ + lcol;
    const float* Wptr = Wih + (size_t)(HID + bx * 128 + lrow) * INSZ + lcol;

    const int ty = tid >> 4;   // 0..15 (m)
    const int tx = tid & 15;   // 0..15 (n)

    float acc[8][8];
#pragma unroll
    for (int i = 0; i < 8; i++)
#pragma unroll
        for (int j = 0; j < 8; j++) acc[i][j] = 0.f;

    for (int k0 = 0; k0 < INSZ; k0 += 8) {
        float4 av = *(const float4*)(Aptr + k0);
        float4 bv = *(const float4*)(Wptr + k0);
        As[lcol + 0][lrow] = av.x;
        As[lcol + 1][lrow] = av.y;
        As[lcol + 2][lrow] = av.z;
        As[lcol + 3][lrow] = av.w;
        Bs[lcol + 0][lrow] = bv.x;
        Bs[lcol + 1][lrow] = bv.y;
        Bs[lcol + 2][lrow] = bv.z;
        Bs[lcol + 3][lrow] = bv.w;
        __syncthreads();

#pragma unroll
        for (int k = 0; k < 8; k++) {
            float ar[8], br[8];
            *(float4*)(ar)     = *(const float4*)&As[k][ty * 8];
            *(float4*)(ar + 4) = *(const float4*)&As[k][ty * 8 + 4];
            *(float4*)(br)     = *(const float4*)&Bs[k][tx * 8];
            *(float4*)(br + 4) = *(const float4*)&Bs[k][tx * 8 + 4];
#pragma unroll
            for (int i = 0; i < 8; i++)
#pragma unroll
                for (int j = 0; j < 8; j++)
                    acc[i][j] = fmaf(ar[i], br[j], acc[i][j]);
        }
        __syncthreads();
    }

    const int n0 = bx * 128 + tx * 8;
    float bv[8];
#pragma unroll
    for (int j = 0; j < 8; j++) bv[j] = bias[HID + n0 + j];

    float* Cpt = g_xp + (size_t)(by * 128 + ty * 8) * GATES + n0;
#pragma unroll
    for (int i = 0; i < 8; i++) {
        float4 o0, o1;
        o0.x = acc[i][0] + bv[0]; o0.y = acc[i][1] + bv[1];
        o0.z = acc[i][2] + bv[2]; o0.w = acc[i][3] + bv[3];
        o1.x = acc[i][4] + bv[4]; o1.y = acc[i][5] + bv[5];
        o1.z = acc[i][6] + bv[6]; o1.w = acc[i][7] + bv[7];
        *(float4*)(Cpt + (size_t)i * GATES)     = o0;
        *(float4*)(Cpt + (size_t)i * GATES + 4) = o1;
    }
}

// ---------------------------------------------------------------------------
// Phase 2: persistent recurrence. 128 CTAs x 256 threads.
// CTA c owns hidden units j in [4c, 4c+4). Thread (b = tid&63, g = tid>>6)
// computes z_(b,j) and n_(b,j) then h_new directly. Grid barrier per step.
// h is broadcast through d_out[(t-1)*BH .. ] (fresh addresses every step).
// ---------------------------------------------------------------------------
extern __shared__ float smem[];

__global__ __launch_bounds__(256) void gru_kernel(
    const float* __restrict__ Whh,   // [3H, HID]
    float* __restrict__ out)         // [S*BH + BH]
{
    float* w_s = smem;               // [8][HID]  z rows then n rows
    float* h_s = smem + 8 * HID;     // [BATCH][HPAD]

    const int tid   = threadIdx.x;
    const int jbase = blockIdx.x * JPER;

    // Load the 8 weight rows this CTA needs (once for the whole sequence).
    for (int i = tid; i < 8 * HID; i += 256) {
        int s = i >> 9, k = i & 511;
        int row = (s < 4) ? (HID + jbase + s) : (2 * HID + jbase + s - 4);
        w_s[i] = Whh[(size_t)row * HID + k];
    }
    // h_0 = 0
    for (int i = tid; i < BATCH * HPAD; i += 256) h_s[i] = 0.f;
    __syncthreads();

    const int b = tid & 63;
    const int g = tid >> 6;          // 0..3
    const int j = jbase + g;
    const float* wz   = w_s + g * HID;
    const float* wn   = w_s + (g + 4) * HID;
    const float* hrow = h_s + b * HPAD;

    for (int t = 0; t < S_LEN; t++) {
        if (t > 0) {
            const float* hsrc = out + (size_t)(t - 1) * BH;
            for (int i = tid * 4; i < BH; i += 1024) {
                int bb = i >> 9, kk = i & 511;
                float4 v = *(const float4*)(hsrc + i);
                *(float4*)(h_s + bb * HPAD + kk) = v;
            }
        }
        __syncthreads();

        float accz = 0.f, accn = 0.f;
#pragma unroll 4
        for (int k = 0; k < HID; k += 4) {
            float4 h4 = *(const float4*)(hrow + k);
            float4 z4 = *(const float4*)(wz + k);
            float4 n4 = *(const float4*)(wn + k);
            accz = fmaf(h4.x, z4.x, accz);
            accz = fmaf(h4.y, z4.y, accz);
            accz = fmaf(h4.z, z4.z, accz);
            accz = fmaf(h4.w, z4.w, accz);
            accn = fmaf(h4.x, n4.x, accn);
            accn = fmaf(h4.y, n4.y, accn);
            accn = fmaf(h4.z, n4.z, accn);
            accn = fmaf(h4.w, n4.w, accn);
        }

        const float* xprow = g_xp + ((size_t)t * BATCH + b) * GATES;
        float gz = accz + xprow[j];
        float gn = accn + xprow[HID + j];
        float z  = 1.f / (1.f + expf(-gz));
        float n  = tanhf(gn);
        float hold = hrow[j];
        float hn = (1.f - z) * n + z * hold;

        out[(size_t)t * BH + b * HID + j] = hn;
        if (t == S_LEN - 1)
            out[(size_t)S_LEN * BH + b * HID + j] = hn;

        // ---- grid-wide barrier (monotonic count, reset per launch) ----
        __syncthreads();
        if (tid == 0) {
            __threadfence();
            unsigned target = (unsigned)(t + 1) * GCTA;
            unsigned old = atomicAdd(&g_count, 1u);
            if (old == target - 1u) {
                __threadfence();
                *((volatile unsigned*)&g_sense) = (unsigned)(t + 1);
            } else {
                while (*((volatile unsigned*)&g_sense) < (unsigned)(t + 1)) {}
            }
            __threadfence();
        }
        __syncthreads();
    }
}

extern "C" void kernel_launch(void* const* d_in, const int* in_sizes, int n_in,
                              void* d_out, int out_size) {
    const float* x    = (const float*)d_in[0];
    const float* wih  = (const float*)d_in[1];
    const float* whh  = (const float*)d_in[2];
    const float* bias = (const float*)d_in[3];
    float* out = (float*)d_out;

    static int configured = 0;
    if (!configured) {
        cudaFuncSetAttribute(gru_kernel,
                             cudaFuncAttributeMaxDynamicSharedMemorySize,
                             (8 * HID + BATCH * HPAD) * sizeof(float));
        configured = 1;
    }

    reset_kernel<<<1, 1>>>();

    dim3 grid1(GATES / 128, M_TOT / 128);
    xproj_kernel<<<grid1, 256>>>(x, wih, bias);

    size_t smem_bytes = (8 * HID + BATCH * HPAD) * sizeof(float);
    gru_kernel<<<GCTA, 256, smem_bytes>>>(whh, out);
}